// round 7
// baseline (speedup 1.0000x reference)
#include <cuda_runtime.h>
#include <cstdint>

#define N_NODES 100000
#define N_EDGES 1600000
#define NCOL 64      // 10 one-hot + 54 mlp
#define HID 128
#define MAXB 128     // max breakpoints
#define MAXSEG 129   // MAXB + 1
#define LUTN 1024

// -------- device-global scratch (allowed; no runtime allocation) --------
__device__ float g_bnd[MAXB + 1];       // sorted breakpoints, padded +INF (incl. [128])
__device__ int   g_nb;                  // number of valid breakpoints
__device__ int   g_is64;                // edge_index stored as int64?
__device__ unsigned char g_lut[LUTN];   // dist-cell -> lower bound on segment id
__device__ __align__(16) float g_A[MAXSEG * NCOL];   // per-segment slope  (cols 0..9 zero)
__device__ __align__(16) float g_B[MAXSEG * NCOL];   // per-segment offset (cols 0..9 zero)
__device__ __align__(16) float g_d[(size_t)N_NODES * NCOL];  // per-node reciprocals of segment sums
__device__ int   g_cnt[N_NODES];        // edges per node
__device__ int   g_basep[N_NODES];      // CSR base offsets
__device__ int   g_cur[N_NODES];        // fill cursors
__device__ float g_csr_dist[N_EDGES];   // dist grouped by src node

// -------- zero counters --------
__global__ void k_zero_cnt() {
    int i = blockIdx.x * blockDim.x + threadIdx.x;
    if (i < N_NODES) g_cnt[i] = 0;
}

// -------- init: detect idx dtype, sorted breakpoints, segment LUT --------
__global__ void k_init(const int* __restrict__ eip,
                       const float* __restrict__ W1, const float* __restrict__ b1) {
    __shared__ float t[HID];
    __shared__ int   vld[HID];
    __shared__ float sorted[HID + 1];
    int j = threadIdx.x;                 // 128 threads

    if (j < 32) {
        // int64 little-endian with values < 2^31 -> all odd 32-bit words are 0.
        unsigned m = __ballot_sync(0xffffffffu, eip[2 * j + 1] != 0);
        if (j == 0) g_is64 = (m == 0) ? 1 : 0;
    }

    float w = W1[j], b = b1[j];
    float tj = -b / w;
    int v = (w != 0.f) && (tj > 0.f) && (tj < 10.f);   // NaN excluded by compares
    t[j] = tj;
    vld[j] = v;
    sorted[j] = __int_as_float(0x7f800000);            // +INF padding
    if (j == 0) sorted[HID] = __int_as_float(0x7f800000);
    __syncthreads();
    int rank = 0, nb = 0;
    for (int i = 0; i < HID; i++) {
        if (vld[i]) {
            nb++;
            if (t[i] < t[j] || (t[i] == t[j] && i < j)) rank++;
        }
    }
    __syncthreads();
    if (v) sorted[rank] = t[j];
    __syncthreads();
    g_bnd[j] = sorted[j];
    if (j == 0) { g_bnd[HID] = sorted[HID]; g_nb = nb; }

    // LUT: conservative lower bound of segment id at each cell start.
    // Deflated threshold guarantees we only UNDERestimate (advance loop fixes it).
    #pragma unroll
    for (int k = 0; k < LUTN / HID; k++) {
        int cell = j * (LUTN / HID) + k;
        float thresh = (float)cell * (10.0f / LUTN) * 0.999999f - 1e-6f;
        int cnt = 0;
        for (int i = 0; i < HID; i++)
            cnt += (sorted[i] < thresh) ? 1 : 0;
        g_lut[cell] = (unsigned char)cnt;
    }
}

// -------- per-segment affine coefficients: w_mlp[k] = relu(A*dist + B) --------
__global__ void __launch_bounds__(256) k_coeffs(
        const float* __restrict__ W1, const float* __restrict__ b1,
        const float* __restrict__ W2, const float* __restrict__ b2) {
    __shared__ float sW1[HID], sb1[HID], sb2[54];
    __shared__ float sW2[HID * 54];
    for (int i = threadIdx.x; i < HID * 54; i += 256) sW2[i] = W2[i];
    if (threadIdx.x < HID) { sW1[threadIdx.x] = W1[threadIdx.x]; sb1[threadIdx.x] = b1[threadIdx.x]; }
    if (threadIdx.x < 54)  sb2[threadIdx.x] = b2[threadIdx.x];
    __syncthreads();

    int seg = blockIdx.x * 4 + (threadIdx.x >> 6);   // 0..131
    int col = threadIdx.x & 63;                      // 0..63
    if (seg >= MAXSEG) return;
    int nb = g_nb;
    float A = 0.f, B = 0.f;
    if (seg <= nb && col >= 10) {
        int m = col - 10;        // 0..53
        float lo = (seg == 0) ? 0.f  : g_bnd[seg - 1];
        float hi = (seg == nb) ? 10.f : g_bnd[seg];
        float x  = 0.5f * (lo + hi);   // interior point -> exact active set
        B = sb2[m];
        #pragma unroll 8
        for (int j = 0; j < HID; j++) {
            float w1 = sW1[j], bb = sb1[j];
            if (fmaf(w1, x, bb) > 0.f) {
                float w2 = sW2[j * 54 + m];
                A = fmaf(w1, w2, A);
                B = fmaf(bb, w2, B);
            }
        }
    }
    g_A[seg * NCOL + col] = A;
    g_B[seg * NCOL + col] = B;
}

// -------- CSR build: histogram of src --------
__global__ void __launch_bounds__(256) k_hist(const int* __restrict__ eip) {
    const int is64 = g_is64;
    int stride = gridDim.x * 256;
    for (int e = blockIdx.x * 256 + threadIdx.x; e < N_EDGES; e += stride) {
        int src = is64 ? __ldg(eip + 2 * e) : __ldg(eip + e);
        atomicAdd(&g_cnt[src], 1);
    }
}

// -------- CSR build: exclusive prefix sum (single block) --------
__global__ void __launch_bounds__(1024) k_scan() {
    __shared__ int part[1024];
    const int CH = (N_NODES + 1023) / 1024;   // 98
    int t = threadIdx.x;
    int start = t * CH;
    int end = start + CH; if (end > N_NODES) end = N_NODES;
    int s = 0;
    for (int i = start; i < end; i++) s += g_cnt[i];
    part[t] = s;
    __syncthreads();
    for (int off = 1; off < 1024; off <<= 1) {
        int v = (t >= off) ? part[t - off] : 0;
        __syncthreads();
        part[t] += v;
        __syncthreads();
    }
    int base = part[t] - s;                   // exclusive prefix of this chunk
    for (int i = start; i < end; i++) {
        int c = g_cnt[i];
        g_basep[i] = base;
        g_cur[i]   = base;
        base += c;
    }
}

// -------- CSR build: fill dist values grouped by src --------
__global__ void __launch_bounds__(256) k_fill(const float* __restrict__ edge_attr,
                                              const int* __restrict__ eip) {
    const int is64 = g_is64;
    int stride = gridDim.x * 256;
    for (int e = blockIdx.x * 256 + threadIdx.x; e < N_EDGES; e += stride) {
        int src = is64 ? __ldg(eip + 2 * e) : __ldg(eip + e);
        int p = atomicAdd(&g_cur[src], 1);
        g_csr_dist[p] = __ldg(edge_attr + e);
    }
}

// -------- per-node register accumulation of d, then reciprocal, store --------
// 16 threads per node (thread owns 4 columns); no atomics anywhere.
__global__ void __launch_bounds__(256)
k_aggr() {
    __shared__ float sbnd[MAXB + 1];
    __shared__ unsigned char slut[LUTN];
    if (threadIdx.x < MAXB + 1) sbnd[threadIdx.x] = g_bnd[threadIdx.x];
    for (int i = threadIdx.x; i < LUTN; i += 256) slut[i] = g_lut[i];
    __syncthreads();

    int node = blockIdx.x * 16 + (threadIdx.x >> 4);
    int c    = threadIdx.x & 15;
    if (node >= N_NODES) return;
    int beg = g_basep[node];
    int cnt = g_cnt[node];

    float4 acc = make_float4(0.f, 0.f, 0.f, 0.f);
    for (int i = 0; i < cnt; i++) {
        float dist = __ldg(g_csr_dist + beg + i);   // broadcast across 16 threads

        int cell = (int)(dist * (LUTN / 10.0f));
        cell = (cell < 0) ? 0 : ((cell > LUTN - 1) ? LUTN - 1 : cell);
        int pos = slut[cell];
        while (sbnd[pos] < dist) pos++;

        const float4 a4 = __ldg((const float4*)(g_A + pos * NCOL + c * 4));
        const float4 b4 = __ldg((const float4*)(g_B + pos * NCOL + c * 4));
        acc.x += fmaxf(fmaf(a4.x, dist, b4.x), 0.f);
        acc.y += fmaxf(fmaf(a4.y, dist, b4.y), 0.f);
        acc.z += fmaxf(fmaf(a4.z, dist, b4.z), 0.f);
        acc.w += fmaxf(fmaf(a4.w, dist, b4.w), 0.f);

        int bucket = (int)dist;
        if (bucket > 9) bucket = 9;
        if ((bucket >> 2) == c) {
            int lb = bucket & 3;
            if      (lb == 0) acc.x += 1.f;
            else if (lb == 1) acc.y += 1.f;
            else if (lb == 2) acc.z += 1.f;
            else              acc.w += 1.f;
        }
    }
    acc.x = (acc.x != 0.f) ? 1.f / acc.x : 0.f;
    acc.y = (acc.y != 0.f) ? 1.f / acc.y : 0.f;
    acc.z = (acc.z != 0.f) ? 1.f / acc.z : 0.f;
    acc.w = (acc.w != 0.f) ? 1.f / acc.w : 0.f;
    ((float4*)g_d)[node * (NCOL / 4) + c] = acc;
}

// -------- gather: recompute w, multiply by reciprocal d[src], store out --------
__global__ void __launch_bounds__(256)
k_gather(const float* __restrict__ edge_attr, const int* __restrict__ eip,
         float4* __restrict__ out) {
    __shared__ float sbnd[MAXB + 1];
    __shared__ unsigned char slut[LUTN];
    if (threadIdx.x < MAXB + 1) sbnd[threadIdx.x] = g_bnd[threadIdx.x];
    for (int i = threadIdx.x; i < LUTN; i += 256) slut[i] = g_lut[i];
    __syncthreads();

    const int is64 = g_is64;
    const unsigned total  = (unsigned)N_EDGES * 16u;
    const unsigned stride = gridDim.x * 256u;
    for (unsigned idx = blockIdx.x * 256u + threadIdx.x; idx < total; idx += stride) {
        int e = (int)(idx >> 4);
        int c = (int)(idx & 15u);
        float dist = __ldg(edge_attr + e);
        int src = is64 ? __ldg(eip + 2 * e) : __ldg(eip + e);

        int cell = (int)(dist * (LUTN / 10.0f));
        cell = (cell < 0) ? 0 : ((cell > LUTN - 1) ? LUTN - 1 : cell);
        int pos = slut[cell];
        while (sbnd[pos] < dist) pos++;

        const float4 a4 = __ldg((const float4*)(g_A + pos * NCOL + c * 4));
        const float4 b4 = __ldg((const float4*)(g_B + pos * NCOL + c * 4));
        float4 w;
        w.x = fmaxf(fmaf(a4.x, dist, b4.x), 0.f);
        w.y = fmaxf(fmaf(a4.y, dist, b4.y), 0.f);
        w.z = fmaxf(fmaf(a4.z, dist, b4.z), 0.f);
        w.w = fmaxf(fmaf(a4.w, dist, b4.w), 0.f);

        int bucket = (int)dist;
        if (bucket > 9) bucket = 9;
        if ((bucket >> 2) == c) {
            int lb = bucket & 3;
            if      (lb == 0) w.x += 1.f;
            else if (lb == 1) w.y += 1.f;
            else if (lb == 2) w.z += 1.f;
            else              w.w += 1.f;
        }

        const float4 di = __ldg((const float4*)g_d + src * (NCOL / 4) + c);
        float4 o = make_float4(w.x * di.x, w.y * di.y, w.z * di.z, w.w * di.w);
        __stcs(out + idx, o);               // streaming: don't evict d from L2
    }
}

extern "C" void kernel_launch(void* const* d_in, const int* in_sizes, int n_in,
                              void* d_out, int out_size) {
    // metadata order: x, edge_index, edge_attr, W1, b1, W2, b2
    const int*   eip       = (const int*)d_in[1];
    const float* edge_attr = (const float*)d_in[2];
    const float* W1        = (const float*)d_in[3];
    const float* b1        = (const float*)d_in[4];
    const float* W2        = (const float*)d_in[5];
    const float* b2        = (const float*)d_in[6];
    (void)in_sizes; (void)n_in; (void)out_size;

    k_zero_cnt<<<(N_NODES + 255) / 256, 256>>>();
    k_init<<<1, HID>>>(eip, W1, b1);
    k_coeffs<<<33, 256>>>(W1, b1, W2, b2);
    k_hist<<<1184, 256>>>(eip);
    k_scan<<<1, 1024>>>();
    k_fill<<<1184, 256>>>(edge_attr, eip);
    k_aggr<<<(N_NODES + 15) / 16, 256>>>();
    k_gather<<<1184, 256>>>(edge_attr, eip, (float4*)d_out);
}

// round 8
// speedup vs baseline: 1.9449x; 1.9449x over previous
#include <cuda_runtime.h>
#include <cstdint>

#define N_NODES 100000
#define N_EDGES 1600000
#define NCOL 64      // 10 one-hot + 54 mlp (one-hot folded into B table)
#define HID 128
#define NCAND 137    // 128 mlp breakpoints + 9 integer bucket boundaries
#define MAXB 144     // padded breakpoint array size
#define MAXSEG 145
#define LUTN 1024

// -------- device-global scratch (allowed; no runtime allocation) --------
__device__ float g_bnd[MAXB + 1];       // sorted breakpoints, +INF padded
__device__ int   g_nb;                  // number of valid breakpoints
__device__ int   g_is64;                // edge_index stored as int64?
__device__ unsigned char g_lut[LUTN];   // dist-cell -> lower bound on segment id
__device__ __align__(16) float g_A[MAXSEG * NCOL];   // per-segment slope
__device__ __align__(16) float g_B[MAXSEG * NCOL];   // per-segment offset (incl. one-hot)
__device__ __align__(16) float g_d[(size_t)N_NODES * NCOL];  // sums -> reciprocals

// -------- init: idx dtype detect, sorted breakpoints (incl ints 1..9), LUT --------
__global__ void k_init(const int* __restrict__ eip,
                       const float* __restrict__ W1, const float* __restrict__ b1) {
    __shared__ float t[NCAND];
    __shared__ int   vld[NCAND];
    __shared__ float sorted[MAXB + 1];
    int j = threadIdx.x;                 // 128 threads

    if (j < 32) {
        // int64 little-endian with values < 2^31 -> all odd 32-bit words are 0.
        unsigned m = __ballot_sync(0xffffffffu, eip[2 * j + 1] != 0);
        if (j == 0) g_is64 = (m == 0) ? 1 : 0;
    }

    // candidates: j<128 from ReLU roots, 128..136 are integers 1..9
    float w = W1[j], b = b1[j];
    float tj = -b / w;
    t[j]   = tj;
    vld[j] = (w != 0.f) && (tj > 0.f) && (tj < 10.f);   // NaN excluded by compares
    if (j < 9) { t[HID + j] = (float)(j + 1); vld[HID + j] = 1; }
    for (int i = j; i < MAXB + 1; i += HID)
        sorted[i] = __int_as_float(0x7f800000);          // +INF padding
    __syncthreads();

    // rank each candidate (thread j owns candidate j, and 128+j if j<9)
    int rank0 = 0, rank1 = 0, nb = 0;
    float t0 = t[j];
    float t1 = (j < 9) ? t[HID + j] : 0.f;
    for (int i = 0; i < NCAND; i++) {
        if (vld[i]) {
            nb++;
            float ti = t[i];
            if (ti < t0 || (ti == t0 && i < j)) rank0++;
            if (j < 9 && (ti < t1 || (ti == t1 && i < HID + j))) rank1++;
        }
    }
    __syncthreads();
    if (vld[j]) sorted[rank0] = t0;
    if (j < 9)  sorted[rank1] = t1;      // integers always valid
    __syncthreads();
    for (int i = j; i < MAXB + 1; i += HID) g_bnd[i] = sorted[i];
    if (j == 0) g_nb = nb;

    // LUT: conservative lower bound of segment id at each cell start.
    // Deflated threshold guarantees we only UNDERestimate (advance loop fixes it).
    #pragma unroll
    for (int k = 0; k < LUTN / HID; k++) {
        int cell = j * (LUTN / HID) + k;
        float thresh = (float)cell * (10.0f / LUTN) * 0.999999f - 1e-6f;
        int cnt = 0;
        for (int i = 0; i < MAXB; i++)
            cnt += (sorted[i] < thresh) ? 1 : 0;
        g_lut[cell] = (unsigned char)cnt;
    }
}

// -------- zero the accumulator --------
__global__ void k_zero() {
    unsigned i = blockIdx.x * blockDim.x + threadIdx.x;
    if (i < (unsigned)(N_NODES * (NCOL / 4)))
        ((float4*)g_d)[i] = make_float4(0.f, 0.f, 0.f, 0.f);
}

// -------- per-segment affine coefficients: w[k] = relu(A*dist + B) --------
// cols 0..9: one-hot baked in (A=0, B=1 on the segment's bucket). 4 segs/block.
__global__ void __launch_bounds__(256) k_coeffs(
        const float* __restrict__ W1, const float* __restrict__ b1,
        const float* __restrict__ W2, const float* __restrict__ b2) {
    __shared__ float sW1[HID], sb1[HID], sb2[54];
    __shared__ float sW2[HID * 54];
    for (int i = threadIdx.x; i < HID * 54; i += 256) sW2[i] = W2[i];
    if (threadIdx.x < HID) { sW1[threadIdx.x] = W1[threadIdx.x]; sb1[threadIdx.x] = b1[threadIdx.x]; }
    if (threadIdx.x < 54)  sb2[threadIdx.x] = b2[threadIdx.x];
    __syncthreads();

    int seg = blockIdx.x * 4 + (threadIdx.x >> 6);   // 0..MAXSEG-1
    int col = threadIdx.x & 63;                      // 0..63
    if (seg >= MAXSEG) return;
    int nb = g_nb;
    float A = 0.f, B = 0.f;
    if (seg <= nb) {
        float lo = (seg == 0) ? 0.f  : g_bnd[seg - 1];
        float hi = (seg == nb) ? 10.f : g_bnd[seg];
        float x  = 0.5f * (lo + hi);   // interior point -> exact active set / bucket
        if (col < 10) {
            int bkt = (int)x;
            if (bkt > 9) bkt = 9;
            if (bkt < 0) bkt = 0;
            B = (bkt == col) ? 1.f : 0.f;
        } else {
            int m = col - 10;        // 0..53
            B = sb2[m];
            #pragma unroll 8
            for (int j = 0; j < HID; j++) {
                float w1 = sW1[j], bb = sb1[j];
                if (fmaf(w1, x, bb) > 0.f) {
                    float w2 = sW2[j * 54 + m];
                    A = fmaf(w1, w2, A);
                    B = fmaf(bb, w2, B);
                }
            }
        }
    }
    g_A[seg * NCOL + col] = A;
    g_B[seg * NCOL + col] = B;
}

// -------- invert accumulator: d -> (d==0 ? 0 : 1/d) --------
__global__ void k_invert() {
    unsigned i = blockIdx.x * blockDim.x + threadIdx.x;
    if (i < (unsigned)(N_NODES * (NCOL / 4))) {
        float4 v = ((float4*)g_d)[i];
        v.x = (v.x != 0.f) ? 1.f / v.x : 0.f;
        v.y = (v.y != 0.f) ? 1.f / v.y : 0.f;
        v.z = (v.z != 0.f) ? 1.f / v.z : 0.f;
        v.w = (v.w != 0.f) ? 1.f / v.w : 0.f;
        ((float4*)g_d)[i] = v;
    }
}

// -------- main: SCATTER (atomic segment-sum) / GATHER (normalize + write) --------
// 8 threads per edge, 2 float4 chunks per thread (c and c+8).
template <bool SCATTER>
__global__ void __launch_bounds__(256)
k_main(const float* __restrict__ edge_attr, const int* __restrict__ eip,
       float4* __restrict__ out) {
    __shared__ float sbnd[MAXB + 1];
    __shared__ unsigned char slut[LUTN];
    for (int i = threadIdx.x; i < MAXB + 1; i += 256) sbnd[i] = g_bnd[i];
    for (int i = threadIdx.x; i < LUTN; i += 256) slut[i] = g_lut[i];
    __syncthreads();

    const int sh = g_is64;               // shift: int64 -> stride-2 words
    const unsigned total  = (unsigned)N_EDGES * 8u;
    const unsigned stride = gridDim.x * 256u;
    for (unsigned idx = blockIdx.x * 256u + threadIdx.x; idx < total; idx += stride) {
        int e = (int)(idx >> 3);
        int c = (int)(idx & 7u);
        float dist = __ldg(edge_attr + e);
        int src = __ldg(eip + (e << sh));

        // segment id = #(bnd < dist): LUT lower bound + exact advance
        int cell = (int)(dist * (LUTN / 10.0f));
        cell = (cell < 0) ? 0 : ((cell > LUTN - 1) ? LUTN - 1 : cell);
        int pos = slut[cell];
        while (sbnd[pos] < dist) pos++;          // bnd padded +INF

        const float4* pa = (const float4*)g_A + pos * 16 + c;
        const float4* pb = (const float4*)g_B + pos * 16 + c;
        const float4 a0 = __ldg(pa),     b0 = __ldg(pb);
        const float4 a1 = __ldg(pa + 8), b1 = __ldg(pb + 8);
        float4 w0, w1;
        w0.x = fmaxf(fmaf(a0.x, dist, b0.x), 0.f);
        w0.y = fmaxf(fmaf(a0.y, dist, b0.y), 0.f);
        w0.z = fmaxf(fmaf(a0.z, dist, b0.z), 0.f);
        w0.w = fmaxf(fmaf(a0.w, dist, b0.w), 0.f);
        w1.x = fmaxf(fmaf(a1.x, dist, b1.x), 0.f);
        w1.y = fmaxf(fmaf(a1.y, dist, b1.y), 0.f);
        w1.z = fmaxf(fmaf(a1.z, dist, b1.z), 0.f);
        w1.w = fmaxf(fmaf(a1.w, dist, b1.w), 0.f);

        if (SCATTER) {
            float* dst = g_d + src * NCOL + c * 4;
            asm volatile("red.global.add.v4.f32 [%0], {%1,%2,%3,%4};"
                         :: "l"(dst), "f"(w0.x), "f"(w0.y), "f"(w0.z), "f"(w0.w)
                         : "memory");
            asm volatile("red.global.add.v4.f32 [%0], {%1,%2,%3,%4};"
                         :: "l"(dst + 32), "f"(w1.x), "f"(w1.y), "f"(w1.z), "f"(w1.w)
                         : "memory");
        } else {
            const float4* pd = (const float4*)g_d + src * 16 + c;
            const float4 d0 = __ldg(pd), d1 = __ldg(pd + 8);
            float4 o0 = make_float4(w0.x * d0.x, w0.y * d0.y, w0.z * d0.z, w0.w * d0.w);
            float4 o1 = make_float4(w1.x * d1.x, w1.y * d1.y, w1.z * d1.z, w1.w * d1.w);
            __stcs(out + e * 16 + c, o0);        // streaming: don't evict d from L2
            __stcs(out + e * 16 + c + 8, o1);
        }
    }
}

extern "C" void kernel_launch(void* const* d_in, const int* in_sizes, int n_in,
                              void* d_out, int out_size) {
    // metadata order: x, edge_index, edge_attr, W1, b1, W2, b2
    const int*   eip       = (const int*)d_in[1];
    const float* edge_attr = (const float*)d_in[2];
    const float* W1        = (const float*)d_in[3];
    const float* b1        = (const float*)d_in[4];
    const float* W2        = (const float*)d_in[5];
    const float* b2        = (const float*)d_in[6];
    (void)in_sizes; (void)n_in; (void)out_size;

    const int nq4 = N_NODES * (NCOL / 4);      // 1.6M float4s in d

    k_init<<<1, HID>>>(eip, W1, b1);
    k_zero<<<(nq4 + 255) / 256, 256>>>();
    k_coeffs<<<(MAXSEG + 3) / 4, 256>>>(W1, b1, W2, b2);
    k_main<true><<<1184, 256>>>(edge_attr, eip, nullptr);
    k_invert<<<(nq4 + 255) / 256, 256>>>();
    k_main<false><<<1184, 256>>>(edge_attr, eip, (float4*)d_out);
}

// round 10
// speedup vs baseline: 2.0213x; 1.0393x over previous
#include <cuda_runtime.h>
#include <cstdint>

#define N_NODES 100000
#define N_EDGES 1600000
#define NCOL 64      // 10 one-hot + 54 mlp (one-hot folded into B table)
#define HID 128
#define NCAND 137    // 128 mlp breakpoints + 9 integer bucket boundaries
#define MAXB 144     // padded breakpoint array size
#define MAXSEG 145
#define LUTN 1024

// -------- device-global scratch (allowed; no runtime allocation) --------
__device__ float g_bnd[MAXB + 1];       // sorted breakpoints, +INF padded
__device__ int   g_nb;                  // number of valid breakpoints
__device__ int   g_is64;                // edge_index stored as int64?
__device__ unsigned char g_lut[LUTN];   // dist-cell -> lower bound on segment id
__device__ __align__(16) float g_A[MAXSEG * NCOL];   // per-segment slope
__device__ __align__(16) float g_B[MAXSEG * NCOL];   // per-segment offset (incl. one-hot)
__device__ __align__(16) float g_d[(size_t)N_NODES * NCOL];  // sums -> reciprocals

// -------- init: idx dtype detect, sorted breakpoints (incl ints 1..9), LUT --------
__global__ void k_init(const int* __restrict__ eip,
                       const float* __restrict__ W1, const float* __restrict__ b1) {
    __shared__ float t[NCAND];
    __shared__ int   vld[NCAND];
    __shared__ float sorted[MAXB + 1];
    int j = threadIdx.x;                 // 128 threads

    if (j < 32) {
        // int64 little-endian with values < 2^31 -> all odd 32-bit words are 0.
        unsigned m = __ballot_sync(0xffffffffu, eip[2 * j + 1] != 0);
        if (j == 0) g_is64 = (m == 0) ? 1 : 0;
    }

    // candidates: j<128 from ReLU roots; 128..136 are integer bucket boundaries.
    // Integer boundary n stored as nextafter(n, 0): since no float lies strictly
    // between nextafter(n,0) and n, the strict test (bnd < dist) becomes exactly
    // (dist >= n), matching reference floor(dist) semantics INCLUDING dist == n.
    float w = W1[j], b = b1[j];
    float tj = -b / w;
    t[j]   = tj;
    vld[j] = (w != 0.f) && (tj > 0.f) && (tj < 10.f);   // NaN excluded by compares
    if (j < 9) {
        float n = (float)(j + 1);
        t[HID + j] = __uint_as_float(__float_as_uint(n) - 1u);  // nextafter(n, 0)
        vld[HID + j] = 1;
    }
    for (int i = j; i < MAXB + 1; i += HID)
        sorted[i] = __int_as_float(0x7f800000);          // +INF padding
    __syncthreads();

    // rank each candidate (thread j owns candidate j, and 128+j if j<9)
    int rank0 = 0, rank1 = 0, nb = 0;
    float t0 = t[j];
    float t1 = (j < 9) ? t[HID + j] : 0.f;
    for (int i = 0; i < NCAND; i++) {
        if (vld[i]) {
            nb++;
            float ti = t[i];
            if (ti < t0 || (ti == t0 && i < j)) rank0++;
            if (j < 9 && (ti < t1 || (ti == t1 && i < HID + j))) rank1++;
        }
    }
    __syncthreads();
    if (vld[j]) sorted[rank0] = t0;
    if (j < 9)  sorted[rank1] = t1;      // integers always valid
    __syncthreads();
    for (int i = j; i < MAXB + 1; i += HID) g_bnd[i] = sorted[i];
    if (j == 0) g_nb = nb;

    // LUT: conservative lower bound of segment id at each cell start.
    // Deflated threshold guarantees we only UNDERestimate (advance loop fixes it).
    #pragma unroll
    for (int k = 0; k < LUTN / HID; k++) {
        int cell = j * (LUTN / HID) + k;
        float thresh = (float)cell * (10.0f / LUTN) * 0.999999f - 1e-6f;
        int cnt = 0;
        for (int i = 0; i < MAXB; i++)
            cnt += (sorted[i] < thresh) ? 1 : 0;
        g_lut[cell] = (unsigned char)cnt;
    }
}

// -------- zero the accumulator --------
__global__ void k_zero() {
    unsigned i = blockIdx.x * blockDim.x + threadIdx.x;
    if (i < (unsigned)(N_NODES * (NCOL / 4)))
        ((float4*)g_d)[i] = make_float4(0.f, 0.f, 0.f, 0.f);
}

// -------- per-segment affine coefficients: w[k] = relu(A*dist + B) --------
// cols 0..9: one-hot baked in (A=0, B=1 on the segment's bucket). 4 segs/block.
__global__ void __launch_bounds__(256) k_coeffs(
        const float* __restrict__ W1, const float* __restrict__ b1,
        const float* __restrict__ W2, const float* __restrict__ b2) {
    __shared__ float sW1[HID], sb1[HID], sb2[54];
    __shared__ float sW2[HID * 54];
    for (int i = threadIdx.x; i < HID * 54; i += 256) sW2[i] = W2[i];
    if (threadIdx.x < HID) { sW1[threadIdx.x] = W1[threadIdx.x]; sb1[threadIdx.x] = b1[threadIdx.x]; }
    if (threadIdx.x < 54)  sb2[threadIdx.x] = b2[threadIdx.x];
    __syncthreads();

    int seg = blockIdx.x * 4 + (threadIdx.x >> 6);   // 0..MAXSEG-1
    int col = threadIdx.x & 63;                      // 0..63
    if (seg >= MAXSEG) return;
    int nb = g_nb;
    float A = 0.f, B = 0.f;
    if (seg <= nb) {
        float lo = (seg == 0) ? 0.f  : g_bnd[seg - 1];
        float hi = (seg == nb) ? 10.f : g_bnd[seg];
        float x  = 0.5f * (lo + hi);   // interior point -> exact active set / bucket
        if (col < 10) {
            // bucket for this segment: count integer boundaries at/below lo.
            // lo is nextafter(n,0)-adjusted, so bucket = #(n: nextafter(n,0) <= lo).
            int bkt = (int)(lo + 1e-6f);          // lo in [n-ulp, n+...) -> n
            if (bkt > 9) bkt = 9;
            if (bkt < 0) bkt = 0;
            B = (bkt == col) ? 1.f : 0.f;
        } else {
            int m = col - 10;        // 0..53
            B = sb2[m];
            #pragma unroll 8
            for (int j = 0; j < HID; j++) {
                float w1 = sW1[j], bb = sb1[j];
                if (fmaf(w1, x, bb) > 0.f) {
                    float w2 = sW2[j * 54 + m];
                    A = fmaf(w1, w2, A);
                    B = fmaf(bb, w2, B);
                }
            }
        }
    }
    g_A[seg * NCOL + col] = A;
    g_B[seg * NCOL + col] = B;
}

// -------- invert accumulator: d -> (d==0 ? 0 : 1/d) --------
__global__ void k_invert() {
    unsigned i = blockIdx.x * blockDim.x + threadIdx.x;
    if (i < (unsigned)(N_NODES * (NCOL / 4))) {
        float4 v = ((float4*)g_d)[i];
        v.x = (v.x != 0.f) ? 1.f / v.x : 0.f;
        v.y = (v.y != 0.f) ? 1.f / v.y : 0.f;
        v.z = (v.z != 0.f) ? 1.f / v.z : 0.f;
        v.w = (v.w != 0.f) ? 1.f / v.w : 0.f;
        ((float4*)g_d)[i] = v;
    }
}

// -------- main: SCATTER (atomic segment-sum) / GATHER (normalize + write) --------
// 8 threads per edge, 2 float4 chunks per thread (c and c+8).
template <bool SCATTER>
__global__ void __launch_bounds__(256)
k_main(const float* __restrict__ edge_attr, const int* __restrict__ eip,
       float4* __restrict__ out) {
    __shared__ float sbnd[MAXB + 1];
    __shared__ unsigned char slut[LUTN];
    for (int i = threadIdx.x; i < MAXB + 1; i += 256) sbnd[i] = g_bnd[i];
    for (int i = threadIdx.x; i < LUTN; i += 256) slut[i] = g_lut[i];
    __syncthreads();

    const int sh = g_is64;               // shift: int64 -> stride-2 words
    const unsigned total  = (unsigned)N_EDGES * 8u;
    const unsigned stride = gridDim.x * 256u;
    for (unsigned idx = blockIdx.x * 256u + threadIdx.x; idx < total; idx += stride) {
        int e = (int)(idx >> 3);
        int c = (int)(idx & 7u);
        float dist = __ldg(edge_attr + e);
        int src = __ldg(eip + (e << sh));

        // segment id = #(bnd < dist): LUT lower bound + exact advance
        int cell = (int)(dist * (LUTN / 10.0f));
        cell = (cell < 0) ? 0 : ((cell > LUTN - 1) ? LUTN - 1 : cell);
        int pos = slut[cell];
        while (sbnd[pos] < dist) pos++;          // bnd padded +INF

        const float4* pa = (const float4*)g_A + pos * 16 + c;
        const float4* pb = (const float4*)g_B + pos * 16 + c;
        const float4 a0 = __ldg(pa),     b0 = __ldg(pb);
        const float4 a1 = __ldg(pa + 8), b1 = __ldg(pb + 8);
        float4 w0, w1;
        w0.x = fmaxf(fmaf(a0.x, dist, b0.x), 0.f);
        w0.y = fmaxf(fmaf(a0.y, dist, b0.y), 0.f);
        w0.z = fmaxf(fmaf(a0.z, dist, b0.z), 0.f);
        w0.w = fmaxf(fmaf(a0.w, dist, b0.w), 0.f);
        w1.x = fmaxf(fmaf(a1.x, dist, b1.x), 0.f);
        w1.y = fmaxf(fmaf(a1.y, dist, b1.y), 0.f);
        w1.z = fmaxf(fmaf(a1.z, dist, b1.z), 0.f);
        w1.w = fmaxf(fmaf(a1.w, dist, b1.w), 0.f);

        if (SCATTER) {
            float* dst = g_d + src * NCOL + c * 4;
            // skip all-zero chunks: ~13% of REDs (one-hot chunks + dead ReLU runs)
            if ((w0.x != 0.f) | (w0.y != 0.f) | (w0.z != 0.f) | (w0.w != 0.f))
                asm volatile("red.global.add.v4.f32 [%0], {%1,%2,%3,%4};"
                             :: "l"(dst), "f"(w0.x), "f"(w0.y), "f"(w0.z), "f"(w0.w)
                             : "memory");
            if ((w1.x != 0.f) | (w1.y != 0.f) | (w1.z != 0.f) | (w1.w != 0.f))
                asm volatile("red.global.add.v4.f32 [%0], {%1,%2,%3,%4};"
                             :: "l"(dst + 32), "f"(w1.x), "f"(w1.y), "f"(w1.z), "f"(w1.w)
                             : "memory");
        } else {
            const float4* pd = (const float4*)g_d + src * 16 + c;
            const float4 d0 = __ldg(pd), d1 = __ldg(pd + 8);
            float4 o0 = make_float4(w0.x * d0.x, w0.y * d0.y, w0.z * d0.z, w0.w * d0.w);
            float4 o1 = make_float4(w1.x * d1.x, w1.y * d1.y, w1.z * d1.z, w1.w * d1.w);
            __stcs(out + e * 16 + c, o0);        // streaming: don't evict d from L2
            __stcs(out + e * 16 + c + 8, o1);
        }
    }
}

extern "C" void kernel_launch(void* const* d_in, const int* in_sizes, int n_in,
                              void* d_out, int out_size) {
    // metadata order: x, edge_index, edge_attr, W1, b1, W2, b2
    const int*   eip       = (const int*)d_in[1];
    const float* edge_attr = (const float*)d_in[2];
    const float* W1        = (const float*)d_in[3];
    const float* b1        = (const float*)d_in[4];
    const float* W2        = (const float*)d_in[5];
    const float* b2        = (const float*)d_in[6];
    (void)in_sizes; (void)n_in; (void)out_size;

    const int nq4 = N_NODES * (NCOL / 4);      // 1.6M float4s in d

    k_init<<<1, HID>>>(eip, W1, b1);
    k_zero<<<(nq4 + 255) / 256, 256>>>();
    k_coeffs<<<(MAXSEG + 3) / 4, 256>>>(W1, b1, W2, b2);
    k_main<true><<<1184, 256>>>(edge_attr, eip, nullptr);
    k_invert<<<(nq4 + 255) / 256, 256>>>();
    k_main<false><<<1184, 256>>>(edge_attr, eip, (float4*)d_out);
}

// round 11
// speedup vs baseline: 2.1202x; 1.0489x over previous
#include <cuda_runtime.h>
#include <cstdint>

#define N_NODES 100000
#define N_EDGES 1600000
#define NCOL 64      // 10 one-hot + 54 mlp (one-hot folded into B table)
#define HID 128
#define NCAND 137    // 128 mlp breakpoints + 9 integer bucket boundaries
#define MAXB 144     // padded breakpoint array size
#define MAXSEG 145
#define LUTN 1024
#define NCB 37       // coeff blocks: ceil(MAXSEG/4)

// -------- device-global scratch (allowed; no runtime allocation) --------
__device__ float g_bnd[MAXB + 1];       // sorted breakpoints, +INF padded
__device__ int   g_is64;                // edge_index stored as int64?
__device__ unsigned char g_lut[LUTN];   // dist-cell -> lower bound on segment id
__device__ __align__(16) float g_A[MAXSEG * NCOL];   // per-segment slope
__device__ __align__(16) float g_B[MAXSEG * NCOL];   // per-segment offset (incl. one-hot)
__device__ __align__(16) float g_d[(size_t)N_NODES * NCOL];  // sums -> reciprocals

// -------- fused prep: blocks 0..NCB-1 = breakpoints+coeffs, rest zero g_d ----
// Each coeff block recomputes the breakpoint sort locally (removes the
// init->coeffs launch dependency); block 0 publishes g_bnd/g_lut/g_is64.
__global__ void __launch_bounds__(256) k_prep(
        const int* __restrict__ eip,
        const float* __restrict__ W1, const float* __restrict__ b1,
        const float* __restrict__ W2, const float* __restrict__ b2) {
    if (blockIdx.x >= NCB) {
        // -------- zero the accumulator (grid-stride) --------
        const float4 z4 = make_float4(0.f, 0.f, 0.f, 0.f);
        unsigned zb  = blockIdx.x - NCB;
        unsigned nzb = gridDim.x - NCB;
        for (unsigned i = zb * 256u + threadIdx.x; i < (unsigned)(N_NODES * 16);
             i += nzb * 256u)
            ((float4*)g_d)[i] = z4;
        return;
    }

    __shared__ float t[NCAND];
    __shared__ int   vld[NCAND];
    __shared__ float sorted[MAXB + 1];
    __shared__ int   s_nb;
    __shared__ float sW1[HID], sb1[HID], sb2[54];
    __shared__ float sW2[HID * 54];
    int tx = threadIdx.x;

    // ---- stage weights (all 256 threads) ----
    for (int i = tx; i < HID * 54; i += 256) sW2[i] = W2[i];
    if (tx < HID) { sW1[tx] = W1[tx]; sb1[tx] = b1[tx]; }
    if (tx < 54)  sb2[tx] = b2[tx];

    // ---- breakpoint candidates (threads 0..127) ----
    // candidates: j<128 from ReLU roots; 128..136 are integer bucket boundaries.
    // Integer boundary n stored as nextafter(n, 0): since no float lies strictly
    // between nextafter(n,0) and n, the strict test (bnd < dist) becomes exactly
    // (dist >= n), matching reference floor(dist) semantics INCLUDING dist == n.
    int j = tx;
    if (j < HID) {
        float w = W1[j], b = b1[j];
        float tj = -b / w;
        t[j]   = tj;
        vld[j] = (w != 0.f) && (tj > 0.f) && (tj < 10.f);  // NaN excluded
        if (j < 9) {
            float n = (float)(j + 1);
            t[HID + j] = __uint_as_float(__float_as_uint(n) - 1u); // nextafter(n,0)
            vld[HID + j] = 1;
        }
    }
    for (int i = tx; i < MAXB + 1; i += 256)
        sorted[i] = __int_as_float(0x7f800000);           // +INF padding
    if (blockIdx.x == 0 && tx < 32) {
        // int64 little-endian with values < 2^31 -> all odd 32-bit words are 0.
        unsigned m = __ballot_sync(0xffffffffu, eip[2 * tx + 1] != 0);
        if (tx == 0) g_is64 = (m == 0) ? 1 : 0;
    }
    __syncthreads();

    if (j < HID) {
        int rank0 = 0, rank1 = 0, nb = 0;
        float t0 = t[j];
        float t1 = (j < 9) ? t[HID + j] : 0.f;
        for (int i = 0; i < NCAND; i++) {
            if (vld[i]) {
                nb++;
                float ti = t[i];
                if (ti < t0 || (ti == t0 && i < j)) rank0++;
                if (j < 9 && (ti < t1 || (ti == t1 && i < HID + j))) rank1++;
            }
        }
        __syncwarp();   // (ranks use only smem reads; no hazard)
        if (vld[j]) sorted[rank0] = t0;
        if (j < 9)  sorted[rank1] = t1;      // integers always valid
        if (j == 0) s_nb = nb;
    }
    __syncthreads();
    int nb = s_nb;

    // ---- block 0 publishes tables for the main kernels ----
    if (blockIdx.x == 0) {
        for (int i = tx; i < MAXB + 1; i += 256) g_bnd[i] = sorted[i];
        // LUT: conservative lower bound of segment id at each cell start.
        // Deflated threshold -> only UNDERestimates (advance loop fixes it).
        for (int cell = tx; cell < LUTN; cell += 256) {
            float thresh = (float)cell * (10.0f / LUTN) * 0.999999f - 1e-6f;
            int cnt = 0;
            for (int i = 0; i < MAXB; i++)
                cnt += (sorted[i] < thresh) ? 1 : 0;
            g_lut[cell] = (unsigned char)cnt;
        }
    }

    // ---- per-segment affine coefficients: w[k] = relu(A*dist + B) ----
    int seg = blockIdx.x * 4 + (tx >> 6);   // 0..MAXSEG-1 (+pad)
    int col = tx & 63;                      // 0..63
    if (seg >= MAXSEG) return;
    float A = 0.f, B = 0.f;
    if (seg <= nb) {
        float lo = (seg == 0) ? 0.f  : sorted[seg - 1];
        float hi = (seg == nb) ? 10.f : sorted[seg];
        float x  = 0.5f * (lo + hi);   // interior point -> exact active set / bucket
        if (col < 10) {
            int bkt = (int)(lo + 1e-6f);          // lo is nextafter-adjusted
            if (bkt > 9) bkt = 9;
            if (bkt < 0) bkt = 0;
            B = (bkt == col) ? 1.f : 0.f;         // one-hot baked in
        } else {
            int m = col - 10;        // 0..53
            B = sb2[m];
            #pragma unroll 8
            for (int jj = 0; jj < HID; jj++) {
                float w1 = sW1[jj], bb = sb1[jj];
                if (fmaf(w1, x, bb) > 0.f) {
                    float w2 = sW2[jj * 54 + m];
                    A = fmaf(w1, w2, A);
                    B = fmaf(bb, w2, B);
                }
            }
        }
    }
    g_A[seg * NCOL + col] = A;
    g_B[seg * NCOL + col] = B;
}

// -------- invert accumulator: d -> (d==0 ? 0 : 1/d) --------
__global__ void k_invert() {
    unsigned i = blockIdx.x * blockDim.x + threadIdx.x;
    if (i < (unsigned)(N_NODES * (NCOL / 4))) {
        float4 v = ((float4*)g_d)[i];
        v.x = (v.x != 0.f) ? 1.f / v.x : 0.f;
        v.y = (v.y != 0.f) ? 1.f / v.y : 0.f;
        v.z = (v.z != 0.f) ? 1.f / v.z : 0.f;
        v.w = (v.w != 0.f) ? 1.f / v.w : 0.f;
        ((float4*)g_d)[i] = v;
    }
}

// -------- main: SCATTER (atomic segment-sum) / GATHER (normalize + write) --------
// 8 threads per edge, 2 float4 chunks per thread (c and c+8).
template <bool SCATTER>
__global__ void __launch_bounds__(256)
k_main(const float* __restrict__ edge_attr, const int* __restrict__ eip,
       float4* __restrict__ out) {
    __shared__ float sbnd[MAXB + 1];
    __shared__ unsigned char slut[LUTN];
    for (int i = threadIdx.x; i < MAXB + 1; i += 256) sbnd[i] = g_bnd[i];
    for (int i = threadIdx.x; i < LUTN; i += 256) slut[i] = g_lut[i];
    __syncthreads();

    const int sh = g_is64;               // shift: int64 -> stride-2 words
    const unsigned total  = (unsigned)N_EDGES * 8u;
    const unsigned stride = gridDim.x * 256u;
    for (unsigned idx = blockIdx.x * 256u + threadIdx.x; idx < total; idx += stride) {
        int e = (int)(idx >> 3);
        int c = (int)(idx & 7u);
        float dist = __ldg(edge_attr + e);
        int src = __ldg(eip + (e << sh));

        // segment id = #(bnd < dist): LUT lower bound + exact advance
        int cell = (int)(dist * (LUTN / 10.0f));
        cell = (cell < 0) ? 0 : ((cell > LUTN - 1) ? LUTN - 1 : cell);
        int pos = slut[cell];
        while (sbnd[pos] < dist) pos++;          // bnd padded +INF

        const float4* pa = (const float4*)g_A + pos * 16 + c;
        const float4* pb = (const float4*)g_B + pos * 16 + c;
        const float4 a0 = __ldg(pa),     b0 = __ldg(pb);
        const float4 a1 = __ldg(pa + 8), b1 = __ldg(pb + 8);
        float4 w0, w1;
        w0.x = fmaxf(fmaf(a0.x, dist, b0.x), 0.f);
        w0.y = fmaxf(fmaf(a0.y, dist, b0.y), 0.f);
        w0.z = fmaxf(fmaf(a0.z, dist, b0.z), 0.f);
        w0.w = fmaxf(fmaf(a0.w, dist, b0.w), 0.f);
        w1.x = fmaxf(fmaf(a1.x, dist, b1.x), 0.f);
        w1.y = fmaxf(fmaf(a1.y, dist, b1.y), 0.f);
        w1.z = fmaxf(fmaf(a1.z, dist, b1.z), 0.f);
        w1.w = fmaxf(fmaf(a1.w, dist, b1.w), 0.f);

        if (SCATTER) {
            float* dst = g_d + src * NCOL + c * 4;
            // skip all-zero chunks (one-hot chunks + dead ReLU runs)
            if ((w0.x != 0.f) | (w0.y != 0.f) | (w0.z != 0.f) | (w0.w != 0.f))
                asm volatile("red.global.add.v4.f32 [%0], {%1,%2,%3,%4};"
                             :: "l"(dst), "f"(w0.x), "f"(w0.y), "f"(w0.z), "f"(w0.w)
                             : "memory");
            if ((w1.x != 0.f) | (w1.y != 0.f) | (w1.z != 0.f) | (w1.w != 0.f))
                asm volatile("red.global.add.v4.f32 [%0], {%1,%2,%3,%4};"
                             :: "l"(dst + 32), "f"(w1.x), "f"(w1.y), "f"(w1.z), "f"(w1.w)
                             : "memory");
        } else {
            const float4* pd = (const float4*)g_d + src * 16 + c;
            const float4 d0 = __ldg(pd), d1 = __ldg(pd + 8);
            float4 o0 = make_float4(w0.x * d0.x, w0.y * d0.y, w0.z * d0.z, w0.w * d0.w);
            float4 o1 = make_float4(w1.x * d1.x, w1.y * d1.y, w1.z * d1.z, w1.w * d1.w);
            __stcs(out + e * 16 + c, o0);        // streaming: don't evict d from L2
            __stcs(out + e * 16 + c + 8, o1);
        }
    }
}

extern "C" void kernel_launch(void* const* d_in, const int* in_sizes, int n_in,
                              void* d_out, int out_size) {
    // metadata order: x, edge_index, edge_attr, W1, b1, W2, b2
    const int*   eip       = (const int*)d_in[1];
    const float* edge_attr = (const float*)d_in[2];
    const float* W1        = (const float*)d_in[3];
    const float* b1        = (const float*)d_in[4];
    const float* W2        = (const float*)d_in[5];
    const float* b2        = (const float*)d_in[6];
    (void)in_sizes; (void)n_in; (void)out_size;

    const int nq4 = N_NODES * (NCOL / 4);      // 1.6M float4s in d

    k_prep<<<1184, 256>>>(eip, W1, b1, W2, b2);
    k_main<true><<<1184, 256>>>(edge_attr, eip, nullptr);
    k_invert<<<(nq4 + 255) / 256, 256>>>();
    k_main<false><<<1184, 256>>>(edge_attr, eip, (float4*)d_out);
}

// round 12
// speedup vs baseline: 2.1903x; 1.0330x over previous
#include <cuda_runtime.h>
#include <cuda_fp16.h>
#include <cstdint>

#define N_NODES 100000
#define N_EDGES 1600000
#define NCOL 64      // 10 one-hot + 54 mlp (one-hot folded into B table)
#define HID 128
#define NCAND 137    // 128 mlp breakpoints + 9 integer bucket boundaries
#define MAXB 144     // padded breakpoint array size
#define MAXSEG 145
#define LUTN 1024
#define NCB 37       // coeff blocks: ceil(MAXSEG/4)

// -------- device-global scratch (allowed; no runtime allocation) --------
__device__ float g_bnd[MAXB + 1];       // sorted breakpoints, +INF padded
__device__ int   g_is64;                // edge_index stored as int64?
__device__ unsigned char g_lut[LUTN];   // dist-cell -> lower bound on segment id
// A stored fp16, PERMUTED row: byte offset 16c holds chunk c's 4 halves then
// chunk (c+8)'s 4 halves -> one LDG.128 per thread fetches all its A values.
__device__ __align__(128) __half g_Ah[MAXSEG * NCOL];
__device__ __align__(128) float  g_B[MAXSEG * NCOL];  // fp32 offset, midpoint-compensated
__device__ __align__(128) float  g_d[(size_t)N_NODES * NCOL];  // sums -> reciprocals

// -------- fused prep: blocks 0..NCB-1 = breakpoints+coeffs, rest zero g_d ----
__global__ void __launch_bounds__(256) k_prep(
        const int* __restrict__ eip,
        const float* __restrict__ W1, const float* __restrict__ b1,
        const float* __restrict__ W2, const float* __restrict__ b2) {
    if (blockIdx.x >= NCB) {
        const float4 z4 = make_float4(0.f, 0.f, 0.f, 0.f);
        unsigned zb  = blockIdx.x - NCB;
        unsigned nzb = gridDim.x - NCB;
        for (unsigned i = zb * 256u + threadIdx.x; i < (unsigned)(N_NODES * 16);
             i += nzb * 256u)
            ((float4*)g_d)[i] = z4;
        return;
    }

    __shared__ float t[NCAND];
    __shared__ int   vld[NCAND];
    __shared__ float sorted[MAXB + 1];
    __shared__ int   s_nb;
    __shared__ float sW1[HID], sb1[HID], sb2[54];
    __shared__ float sW2[HID * 54];
    int tx = threadIdx.x;

    for (int i = tx; i < HID * 54; i += 256) sW2[i] = W2[i];
    if (tx < HID) { sW1[tx] = W1[tx]; sb1[tx] = b1[tx]; }
    if (tx < 54)  sb2[tx] = b2[tx];

    // breakpoint candidates: j<128 ReLU roots; 128..136 integer boundaries as
    // nextafter(n,0) so the strict test (bnd < dist) == (dist >= n) exactly.
    int j = tx;
    if (j < HID) {
        float w = W1[j], b = b1[j];
        float tj = -b / w;
        t[j]   = tj;
        vld[j] = (w != 0.f) && (tj > 0.f) && (tj < 10.f);  // NaN excluded
        if (j < 9) {
            float n = (float)(j + 1);
            t[HID + j] = __uint_as_float(__float_as_uint(n) - 1u); // nextafter(n,0)
            vld[HID + j] = 1;
        }
    }
    for (int i = tx; i < MAXB + 1; i += 256)
        sorted[i] = __int_as_float(0x7f800000);           // +INF padding
    if (blockIdx.x == 0 && tx < 32) {
        // int64 little-endian values < 2^31 -> all odd 32-bit words are 0.
        unsigned m = __ballot_sync(0xffffffffu, eip[2 * tx + 1] != 0);
        if (tx == 0) g_is64 = (m == 0) ? 1 : 0;
    }
    __syncthreads();

    if (j < HID) {
        int rank0 = 0, rank1 = 0, nb = 0;
        float t0 = t[j];
        float t1 = (j < 9) ? t[HID + j] : 0.f;
        for (int i = 0; i < NCAND; i++) {
            if (vld[i]) {
                nb++;
                float ti = t[i];
                if (ti < t0 || (ti == t0 && i < j)) rank0++;
                if (j < 9 && (ti < t1 || (ti == t1 && i < HID + j))) rank1++;
            }
        }
        __syncwarp();
        if (vld[j]) sorted[rank0] = t0;
        if (j < 9)  sorted[rank1] = t1;
        if (j == 0) s_nb = nb;
    }
    __syncthreads();
    int nb = s_nb;

    if (blockIdx.x == 0) {
        for (int i = tx; i < MAXB + 1; i += 256) g_bnd[i] = sorted[i];
        // LUT: deflated threshold -> only UNDERestimates (advance loop fixes it)
        for (int cell = tx; cell < LUTN; cell += 256) {
            float thresh = (float)cell * (10.0f / LUTN) * 0.999999f - 1e-6f;
            int cnt = 0;
            for (int i = 0; i < MAXB; i++)
                cnt += (sorted[i] < thresh) ? 1 : 0;
            g_lut[cell] = (unsigned char)cnt;
        }
    }

    // per-segment affine coefficients: w[k] = relu(A*dist + B)
    int seg = blockIdx.x * 4 + (tx >> 6);   // 0..MAXSEG-1 (+pad)
    int col = tx & 63;                      // 0..63
    if (seg >= MAXSEG) return;
    float A = 0.f, B = 0.f, x = 0.f;
    if (seg <= nb) {
        float lo = (seg == 0) ? 0.f  : sorted[seg - 1];
        float hi = (seg == nb) ? 10.f : sorted[seg];
        x = 0.5f * (lo + hi);   // interior midpoint -> exact active set / bucket
        if (col < 10) {
            int bkt = (int)(lo + 1e-6f);          // lo is nextafter-adjusted
            if (bkt > 9) bkt = 9;
            if (bkt < 0) bkt = 0;
            B = (bkt == col) ? 1.f : 0.f;         // one-hot baked in
        } else {
            int m = col - 10;        // 0..53
            B = sb2[m];
            #pragma unroll 8
            for (int jj = 0; jj < HID; jj++) {
                float w1 = sW1[jj], bb = sb1[jj];
                if (fmaf(w1, x, bb) > 0.f) {
                    float w2 = sW2[jj * 54 + m];
                    A = fmaf(w1, w2, A);
                    B = fmaf(bb, w2, B);
                }
            }
        }
    }
    // fp16 slope + exact midpoint compensation in fp32 B:
    // w'(x_mid) == w(x_mid); elsewhere |err| <= |A - aq| * seg_halfwidth (~1e-4)
    __half ah = __float2half_rn(A);
    float  aq = __half2float(ah);
    int cc = col >> 2, r = col & 3;
    int apos = (cc < 8) ? (cc * 8 + r) : ((cc - 8) * 8 + 4 + r);  // permuted slot
    g_Ah[seg * NCOL + apos] = ah;
    g_B [seg * NCOL + col]  = fmaf(A - aq, x, B);
}

// -------- invert accumulator: d -> (d==0 ? 0 : 1/d) --------
__global__ void k_invert() {
    unsigned i = blockIdx.x * blockDim.x + threadIdx.x;
    if (i < (unsigned)(N_NODES * (NCOL / 4))) {
        float4 v = ((float4*)g_d)[i];
        v.x = (v.x != 0.f) ? 1.f / v.x : 0.f;
        v.y = (v.y != 0.f) ? 1.f / v.y : 0.f;
        v.z = (v.z != 0.f) ? 1.f / v.z : 0.f;
        v.w = (v.w != 0.f) ? 1.f / v.w : 0.f;
        ((float4*)g_d)[i] = v;
    }
}

// -------- main: SCATTER (atomic segment-sum) / GATHER (normalize + write) --------
// 8 threads per edge, 2 float4 chunks per thread (c and c+8).
template <bool SCATTER>
__global__ void __launch_bounds__(256)
k_main(const float* __restrict__ edge_attr, const int* __restrict__ eip,
       float4* __restrict__ out) {
    __shared__ float sbnd[MAXB + 1];
    __shared__ unsigned char slut[LUTN];
    for (int i = threadIdx.x; i < MAXB + 1; i += 256) sbnd[i] = g_bnd[i];
    for (int i = threadIdx.x; i < LUTN; i += 256) slut[i] = g_lut[i];
    __syncthreads();

    const int sh = g_is64;               // shift: int64 -> stride-2 words
    const unsigned total  = (unsigned)N_EDGES * 8u;
    const unsigned stride = gridDim.x * 256u;
    for (unsigned idx = blockIdx.x * 256u + threadIdx.x; idx < total; idx += stride) {
        int e = (int)(idx >> 3);
        int c = (int)(idx & 7u);
        float dist = __ldg(edge_attr + e);
        int src = __ldg(eip + (e << sh));

        // segment id = #(bnd < dist): LUT lower bound + exact advance
        int cell = (int)(dist * (LUTN / 10.0f));
        cell = (cell < 0) ? 0 : ((cell > LUTN - 1) ? LUTN - 1 : cell);
        int pos = slut[cell];
        while (sbnd[pos] < dist) pos++;          // bnd padded +INF

        // ONE 16B load gets all 8 fp16 slopes (chunk c + chunk c+8, permuted row)
        const uint4 av = __ldg((const uint4*)g_Ah + pos * 8 + c);
        const __half2* hp = (const __half2*)&av;
        const float2 a01 = __half22float2(hp[0]);
        const float2 a23 = __half22float2(hp[1]);
        const float2 a45 = __half22float2(hp[2]);
        const float2 a67 = __half22float2(hp[3]);

        const float4* pb = (const float4*)g_B + pos * 16 + c;
        const float4 b0 = __ldg(pb), b1 = __ldg(pb + 8);
        float4 w0, w1;
        w0.x = fmaxf(fmaf(a01.x, dist, b0.x), 0.f);
        w0.y = fmaxf(fmaf(a01.y, dist, b0.y), 0.f);
        w0.z = fmaxf(fmaf(a23.x, dist, b0.z), 0.f);
        w0.w = fmaxf(fmaf(a23.y, dist, b0.w), 0.f);
        w1.x = fmaxf(fmaf(a45.x, dist, b1.x), 0.f);
        w1.y = fmaxf(fmaf(a45.y, dist, b1.y), 0.f);
        w1.z = fmaxf(fmaf(a67.x, dist, b1.z), 0.f);
        w1.w = fmaxf(fmaf(a67.y, dist, b1.w), 0.f);

        if (SCATTER) {
            float* dst = g_d + src * NCOL + c * 4;
            // skip all-zero chunks (one-hot chunks + dead ReLU runs)
            if ((w0.x != 0.f) | (w0.y != 0.f) | (w0.z != 0.f) | (w0.w != 0.f))
                asm volatile("red.global.add.v4.f32 [%0], {%1,%2,%3,%4};"
                             :: "l"(dst), "f"(w0.x), "f"(w0.y), "f"(w0.z), "f"(w0.w)
                             : "memory");
            if ((w1.x != 0.f) | (w1.y != 0.f) | (w1.z != 0.f) | (w1.w != 0.f))
                asm volatile("red.global.add.v4.f32 [%0], {%1,%2,%3,%4};"
                             :: "l"(dst + 32), "f"(w1.x), "f"(w1.y), "f"(w1.z), "f"(w1.w)
                             : "memory");
        } else {
            const float4* pd = (const float4*)g_d + src * 16 + c;
            const float4 d0 = __ldg(pd), d1 = __ldg(pd + 8);
            float4 o0 = make_float4(w0.x * d0.x, w0.y * d0.y, w0.z * d0.z, w0.w * d0.w);
            float4 o1 = make_float4(w1.x * d1.x, w1.y * d1.y, w1.z * d1.z, w1.w * d1.w);
            __stcs(out + e * 16 + c, o0);        // streaming: don't evict d from L2
            __stcs(out + e * 16 + c + 8, o1);
        }
    }
}

extern "C" void kernel_launch(void* const* d_in, const int* in_sizes, int n_in,
                              void* d_out, int out_size) {
    // metadata order: x, edge_index, edge_attr, W1, b1, W2, b2
    const int*   eip       = (const int*)d_in[1];
    const float* edge_attr = (const float*)d_in[2];
    const float* W1        = (const float*)d_in[3];
    const float* b1        = (const float*)d_in[4];
    const float* W2        = (const float*)d_in[5];
    const float* b2        = (const float*)d_in[6];
    (void)in_sizes; (void)n_in; (void)out_size;

    const int nq4 = N_NODES * (NCOL / 4);      // 1.6M float4s in d

    k_prep<<<1184, 256>>>(eip, W1, b1, W2, b2);
    k_main<true><<<1184, 256>>>(edge_attr, eip, nullptr);
    k_invert<<<(nq4 + 255) / 256, 256>>>();
    k_main<false><<<1184, 256>>>(edge_attr, eip, (float4*)d_out);
}